// round 8
// baseline (speedup 1.0000x reference)
#include <cuda_runtime.h>

// ChamferDistance: B=8, N=M=8192, D=3.
// min_j d = min_j (n_j + x . y'_j) + |x_i|^2,  y' = -2y folded into tile fill.
// Packed fma.rn.f32x2, RX=8 owned points/thread, 8-way j-split -> 512 blocks
// (~27 warps/SM). Deterministic ticket-gated combines. Single kernel launch.

#define TPB    256
#define RX     8
#define CHUNK  (TPB * RX)          // 2048 owned points per block
#define PTS    8192
#define BATCH  8
#define TILE   1024
#define JP     (TILE / 2)          // j-pairs per tile
#define NCHUNK (PTS / CHUNK)       // 4
#define NJS    8                   // j-split factor
#define JSEG   (PTS / NJS)         // 1024 opposing points per block (== TILE)
#define NGROUP (2 * BATCH * NCHUNK)   // 64
#define NBLOCKS (NGROUP * NJS)        // 512

__device__ float    g_pmin[NGROUP * NJS * CHUNK];
__device__ float    g_part[NGROUP];
__device__ unsigned g_gticket[NGROUP];
__device__ unsigned g_fticket;

#define PACK_F32X2(out, lo, hi) \
    asm("mov.b64 %0, {%1, %2};" : "=l"(out) : "f"(lo), "f"(hi))

#define UNPACK_F32X2(lo, hi, in) \
    asm("mov.b64 {%0, %1}, %2;" : "=f"(lo), "=f"(hi) : "l"(in))

#define FMA_F32X2(d, a, b, c) \
    asm("fma.rn.f32x2 %0, %1, %2, %3;" : "=l"(d) : "l"(a), "l"(b), "l"(c))

__global__ __launch_bounds__(TPB)
void chamfer_pass_kernel(const float* __restrict__ x, const float* __restrict__ y,
                         float* __restrict__ out) {
    const int bid   = blockIdx.x;
    const int dir   = bid >> 8;                 // 0..1
    const int batch = (bid >> 5) & 7;           // 0..7
    const int chunk = (bid >> 3) & 3;           // 0..3
    const int js    = bid & 7;                  // 0..7
    const int group = (dir * BATCH + batch) * NCHUNK + chunk;

    const float* __restrict__ ownb = (dir ? y : x) + (size_t)batch * PTS * 3;
    const float* __restrict__ oppb = (dir ? x : y) + (size_t)batch * PTS * 3;

    // Per j-pair: sAB = {(-2a0,-2a1),(-2b0,-2b1)}, sCN = {(-2c0,-2c1),(n0,n1)}
    __shared__ __align__(16) ulonglong2 sAB[JP];
    __shared__ __align__(16) ulonglong2 sCN[JP];

    const int tid = threadIdx.x;

    unsigned long long xa[RX], xb[RX], xc[RX];
    float mnl[RX], mnh[RX];
#pragma unroll
    for (int r = 0; r < RX; r++) {
        int i = chunk * CHUNK + r * TPB + tid;
        float a = ownb[i * 3 + 0];
        float b = ownb[i * 3 + 1];
        float c = ownb[i * 3 + 2];
        PACK_F32X2(xa[r], a, a);
        PACK_F32X2(xb[r], b, b);
        PACK_F32X2(xc[r], c, c);
        mnl[r] = 3.4e38f;
        mnh[r] = 3.4e38f;
    }

    // single tile: JSEG == TILE
    {
        const int jbase = js * JSEG;
#pragma unroll
        for (int jj = tid; jj < TILE; jj += TPB) {
            const float* p = oppb + (size_t)(jbase + jj) * 3;
            float a = p[0], b = p[1], c = p[2];
            float n = fmaf(a, a, fmaf(b, b, c * c));
            int jp = jj >> 1, lane = jj & 1;
            float* pab = (float*)&sAB[jp];
            float* pcn = (float*)&sCN[jp];
            pab[lane + 0] = -2.0f * a;
            pab[lane + 2] = -2.0f * b;
            pcn[lane + 0] = -2.0f * c;
            pcn[lane + 2] = n;
        }
        __syncthreads();

#pragma unroll 4
        for (int jp = 0; jp < JP; ++jp) {
            ulonglong2 ab = sAB[jp];   // LDS.128 broadcast
            ulonglong2 cn = sCN[jp];   // LDS.128 broadcast
#pragma unroll
            for (int r = 0; r < RX; ++r) {
                unsigned long long t;
                FMA_F32X2(t, xc[r], cn.x, cn.y);
                FMA_F32X2(t, xb[r], ab.y, t);
                FMA_F32X2(t, xa[r], ab.x, t);
                float lo, hi;
                UNPACK_F32X2(lo, hi, t);
                mnl[r] = fminf(mnl[r], lo);
                mnh[r] = fminf(mnh[r], hi);
            }
        }
    }

    // publish this j-slice's partial mins
#pragma unroll
    for (int r = 0; r < RX; r++)
        g_pmin[(group * NJS + js) * CHUNK + r * TPB + tid] = fminf(mnl[r], mnh[r]);

    // per-group ticket: 8th arrival combines (fixed order -> deterministic)
    __shared__ bool isComb;
    __threadfence();
    __syncthreads();
    if (tid == 0) {
        unsigned t = atomicAdd(&g_gticket[group], 1u);
        isComb = (t == NJS - 1);
        if (isComb) g_gticket[group] = 0;   // reset for next replay
    }
    __syncthreads();
    if (!isComb) return;
    __threadfence();

    float s = 0.0f;
#pragma unroll
    for (int r = 0; r < RX; r++) {
        int idx = r * TPB + tid;
        float m = 3.4e38f;
#pragma unroll
        for (int ss = 0; ss < NJS; ss++)
            m = fminf(m, g_pmin[(group * NJS + ss) * CHUNK + idx]);
        float x0, x1, x2, d0, d1, d2;
        UNPACK_F32X2(x0, d0, xa[r]);
        UNPACK_F32X2(x1, d1, xb[r]);
        UNPACK_F32X2(x2, d2, xc[r]);
        s += m + fmaf(x0, x0, fmaf(x1, x1, x2 * x2));
    }

    __shared__ float red[TPB];
    red[tid] = s;
    __syncthreads();
#pragma unroll
    for (int o = TPB / 2; o > 0; o >>= 1) {
        if (tid < o) red[tid] += red[tid + o];
        __syncthreads();
    }
    if (tid == 0) g_part[group] = red[0];

    // global ticket over the 64 combiners: last one reduces the scalar
    __shared__ bool isFin;
    __threadfence();
    __syncthreads();
    if (tid == 0) {
        unsigned t = atomicAdd(&g_fticket, 1u);
        isFin = (t == NGROUP - 1);
        if (isFin) g_fticket = 0;   // reset for next replay
    }
    __syncthreads();
    if (!isFin) return;
    __threadfence();

    float v = (tid < NGROUP) ? g_part[tid] : 0.0f;
    red[tid] = v;
    __syncthreads();
#pragma unroll
    for (int o = TPB / 2; o > 0; o >>= 1) {
        if (tid < o) red[tid] += red[tid + o];
        __syncthreads();
    }
    if (tid == 0) out[0] = red[0] * (1.0f / 65536.0f);
}

extern "C" void kernel_launch(void* const* d_in, const int* in_sizes, int n_in,
                              void* d_out, int out_size) {
    const float* x = (const float*)d_in[0];
    const float* y = (const float*)d_in[1];
    float* out = (float*)d_out;

    chamfer_pass_kernel<<<NBLOCKS, TPB>>>(x, y, out);
}

// round 9
// speedup vs baseline: 1.5748x; 1.5748x over previous
#include <cuda_runtime.h>

// ChamferDistance: B=8, N=M=8192, D=3.
// d(i,j) = n_j + (-2x_i).y_j + |x_i|^2 ; min over j per i (both directions).
// Transposed packing: TWO owned points per fma.rn.f32x2 register (coords
// pre-scaled by -2), opposing point broadcast into both lanes via shared tile.
// Fixed regs: 24 (owned) + 8 (mins). RX=8, NJS=4, 256 blocks, 1 launch.

#define TPB    256
#define RX     8
#define NPK    (RX / 2)            // packed owned pairs per thread
#define CHUNK  (TPB * RX)          // 2048 owned points per block
#define PTS    8192
#define BATCH  8
#define TILE   1024
#define NCHUNK (PTS / CHUNK)       // 4
#define NJS    4                   // j-split factor
#define JSEG   (PTS / NJS)         // 2048 opposing points per block
#define NGROUP (2 * BATCH * NCHUNK)   // 64
#define NBLOCKS (NGROUP * NJS)        // 256

__device__ float    g_pmin[NGROUP * NJS * CHUNK];
__device__ float    g_part[NGROUP];
__device__ unsigned g_gticket[NGROUP];
__device__ unsigned g_fticket;

#define PACK_F32X2(out, lo, hi) \
    asm("mov.b64 %0, {%1, %2};" : "=l"(out) : "f"(lo), "f"(hi))

#define UNPACK_F32X2(lo, hi, in) \
    asm("mov.b64 {%0, %1}, %2;" : "=f"(lo), "=f"(hi) : "l"(in))

#define FMA_F32X2(d, a, b, c) \
    asm("fma.rn.f32x2 %0, %1, %2, %3;" : "=l"(d) : "l"(a), "l"(b), "l"(c))

__global__ __launch_bounds__(TPB, 2)
void chamfer_pass_kernel(const float* __restrict__ x, const float* __restrict__ y,
                         float* __restrict__ out) {
    const int bid   = blockIdx.x;
    const int dir   = bid >> 7;                 // 0..1
    const int batch = (bid >> 4) & 7;           // 0..7
    const int chunk = (bid >> 2) & 3;           // 0..3
    const int js    = bid & 3;                  // 0..3
    const int group = (dir * BATCH + batch) * NCHUNK + chunk;

    const float* __restrict__ ownb = (dir ? y : x) + (size_t)batch * PTS * 3;
    const float* __restrict__ oppb = (dir ? x : y) + (size_t)batch * PTS * 3;

    // Per opposing point j: sAB[j] = {(a,a),(b,b)}, sCN[j] = {(c,c),(n,n)}
    __shared__ __align__(16) ulonglong2 sAB[TILE];
    __shared__ __align__(16) ulonglong2 sCN[TILE];

    const int tid = threadIdx.x;

    // Owned points: two points per packed register, coords pre-scaled by -2.
    unsigned long long xa2[NPK], xb2[NPK], xc2[NPK];
    float mn[RX];
#pragma unroll
    for (int p = 0; p < NPK; p++) {
        int i0 = chunk * CHUNK + (2 * p)     * TPB + tid;
        int i1 = chunk * CHUNK + (2 * p + 1) * TPB + tid;
        PACK_F32X2(xa2[p], -2.0f * ownb[i0 * 3 + 0], -2.0f * ownb[i1 * 3 + 0]);
        PACK_F32X2(xb2[p], -2.0f * ownb[i0 * 3 + 1], -2.0f * ownb[i1 * 3 + 1]);
        PACK_F32X2(xc2[p], -2.0f * ownb[i0 * 3 + 2], -2.0f * ownb[i1 * 3 + 2]);
    }
#pragma unroll
    for (int r = 0; r < RX; r++) mn[r] = 3.4e38f;

    const int jbase = js * JSEG;
    for (int t0 = 0; t0 < JSEG; t0 += TILE) {
        __syncthreads();
#pragma unroll
        for (int jj = tid; jj < TILE; jj += TPB) {
            const float* pp = oppb + (size_t)(jbase + t0 + jj) * 3;
            float a = pp[0], b = pp[1], c = pp[2];
            float n = fmaf(a, a, fmaf(b, b, c * c));
            ulonglong2 v0, v1;
            PACK_F32X2(v0.x, a, a);
            PACK_F32X2(v0.y, b, b);
            PACK_F32X2(v1.x, c, c);
            PACK_F32X2(v1.y, n, n);
            sAB[jj] = v0;
            sCN[jj] = v1;
        }
        __syncthreads();

#pragma unroll 4
        for (int j = 0; j < TILE; ++j) {
            ulonglong2 ab = sAB[j];   // LDS.128 broadcast: (a,a),(b,b)
            ulonglong2 cn = sCN[j];   // LDS.128 broadcast: (c,c),(n,n)
#pragma unroll
            for (int p = 0; p < NPK; ++p) {
                unsigned long long t;
                FMA_F32X2(t, xc2[p], cn.x, cn.y);   // (-2c_i)c_j + n_j
                FMA_F32X2(t, xb2[p], ab.y, t);
                FMA_F32X2(t, xa2[p], ab.x, t);
                float lo, hi;
                UNPACK_F32X2(lo, hi, t);
                mn[2 * p]     = fminf(mn[2 * p],     lo);
                mn[2 * p + 1] = fminf(mn[2 * p + 1], hi);
            }
        }
    }

    // publish this j-slice's partial mins (mn[r] belongs to point r*TPB+tid)
#pragma unroll
    for (int r = 0; r < RX; r++)
        g_pmin[(group * NJS + js) * CHUNK + r * TPB + tid] = mn[r];

    // per-group ticket: last arrival combines (fixed order -> deterministic)
    __shared__ bool isComb;
    __threadfence();
    __syncthreads();
    if (tid == 0) {
        unsigned t = atomicAdd(&g_gticket[group], 1u);
        isComb = (t == NJS - 1);
        if (isComb) g_gticket[group] = 0;   // reset for next replay
    }
    __syncthreads();
    if (!isComb) return;
    __threadfence();

    float s = 0.0f;
#pragma unroll
    for (int p = 0; p < NPK; p++) {
        float a0, a1, b0, b1, c0, c1;
        UNPACK_F32X2(a0, a1, xa2[p]);   // = -2 * coord
        UNPACK_F32X2(b0, b1, xb2[p]);
        UNPACK_F32X2(c0, c1, xc2[p]);
        float n0 = 0.25f * fmaf(a0, a0, fmaf(b0, b0, c0 * c0));
        float n1 = 0.25f * fmaf(a1, a1, fmaf(b1, b1, c1 * c1));
#pragma unroll
        for (int h = 0; h < 2; h++) {
            int r = 2 * p + h;
            int idx = r * TPB + tid;
            float m = 3.4e38f;
#pragma unroll
            for (int ss = 0; ss < NJS; ss++)
                m = fminf(m, g_pmin[(group * NJS + ss) * CHUNK + idx]);
            s += m + (h ? n1 : n0);
        }
    }

    __shared__ float red[TPB];
    red[tid] = s;
    __syncthreads();
#pragma unroll
    for (int o = TPB / 2; o > 0; o >>= 1) {
        if (tid < o) red[tid] += red[tid + o];
        __syncthreads();
    }
    if (tid == 0) g_part[group] = red[0];

    // global ticket over the 64 combiners: last one reduces the scalar
    __shared__ bool isFin;
    __threadfence();
    __syncthreads();
    if (tid == 0) {
        unsigned t = atomicAdd(&g_fticket, 1u);
        isFin = (t == NGROUP - 1);
        if (isFin) g_fticket = 0;   // reset for next replay
    }
    __syncthreads();
    if (!isFin) return;
    __threadfence();

    float v = (tid < NGROUP) ? g_part[tid] : 0.0f;
    red[tid] = v;
    __syncthreads();
#pragma unroll
    for (int o = TPB / 2; o > 0; o >>= 1) {
        if (tid < o) red[tid] += red[tid + o];
        __syncthreads();
    }
    if (tid == 0) out[0] = red[0] * (1.0f / 65536.0f);
}

extern "C" void kernel_launch(void* const* d_in, const int* in_sizes, int n_in,
                              void* d_out, int out_size) {
    const float* x = (const float*)d_in[0];
    const float* y = (const float*)d_in[1];
    float* out = (float*)d_out;

    chamfer_pass_kernel<<<NBLOCKS, TPB>>>(x, y, out);
}